// round 8
// baseline (speedup 1.0000x reference)
#include <cuda_runtime.h>
#include <cuda_bf16.h>
#include <math.h>
#include <cstdint>

// Problem dims (fixed by the reference setup_inputs)
#define BB   2
#define NN   1024
#define HG   64            // H*G
#define NBATCH (BB*HG)     // 128 independent GEMM batches
#define NROWS  (BB*NN*HG)  // 131072 SH rows per side
#define KPAD 64            // 48 used (h|h|l or h|l|h), padded to 64 bf16 rows
#define KTOT 48            // active K (3 x 16)

// bf16 hi/lo operand arrays, [batch][n][KPAD], K-contiguous rows
__device__ __nv_bfloat16 g_Abf[(size_t)NBATCH * NN * KPAD];  // q side (scaled)
__device__ __nv_bfloat16 g_Bbf[(size_t)NBATCH * NN * KPAD];  // k side

// ---------------------------------------------------------------------------
// Kernel 1: rotate -> normalize -> SH -> bf16 hi/lo split -> K-padded rows.
//   q side (which=0): cols [h,h,l] of Y/sqrt(15)  -> g_Abf
//   k side (which=1): cols [h,l,h] of Y           -> g_Bbf
// Dot over 48 cols then gives h.h + h.l + l.h  (compensated bf16 product).
// ---------------------------------------------------------------------------
__global__ void sh_expand_kernel(const float* __restrict__ q_in,
                                 const float* __restrict__ k_in,
                                 const float* __restrict__ rq_in,
                                 const float* __restrict__ rk_in)
{
    int gt = blockIdx.x * blockDim.x + threadIdx.x;
    if (gt >= 2 * NROWS) return;
    int which = gt >= NROWS;          // 0 -> q, 1 -> k
    int t = gt - which * NROWS;

    const float* v_in = which ? k_in : q_in;
    const float* r_in = which ? rk_in : rq_in;
    float scale = which ? 1.0f : 0.2581988897471611f;  // 1/sqrt(15)

    int hg = t & (HG - 1);       // h*G + g
    int bn = t >> 6;             // b*N + n
    int b  = bn >> 10;           // /N
    int n  = bn & (NN - 1);

    const float* q = v_in + (size_t)t * 3;
    const float* r = r_in + (size_t)bn * 9;
    float q0 = q[0], q1 = q[1], q2 = q[2];

    float vx = r[0]*q0 + r[1]*q1 + r[2]*q2;
    float vy = r[3]*q0 + r[4]*q1 + r[5]*q2;
    float vz = r[6]*q0 + r[7]*q1 + r[8]*q2;

    float nrm = sqrtf(vx*vx + vy*vy + vz*vz);
    float inv = 1.0f / fmaxf(nrm, 1e-12f);
    float x = vx*inv, y = vy*inv, z = vz*inv;
    float x2 = x*x, y2 = y*y, z2 = z*z;

    const float f1 = 0.4886025119029199f * scale;  // sqrt(3/(4pi))
    const float f2 = 0.6307831305050401f * scale;  // sqrt(5/(4pi))
    const float f3 = 0.7463526651802308f * scale;  // sqrt(7/(4pi))
    const float s3  = 1.7320508075688772f;
    const float s15 = 3.8729833462074170f;
    const float c1  = 0.6123724356957945f;         // sqrt(3/8)
    const float c3  = 0.7905694150420949f;         // sqrt(5/8)

    float yv[15];
    yv[0]  = f1 * x;
    yv[1]  = f1 * y;
    yv[2]  = f1 * z;
    yv[3]  = f2 * (s3 * x * z);
    yv[4]  = f2 * (s3 * x * y);
    yv[5]  = f2 * (y2 - 0.5f * (x2 + z2));
    yv[6]  = f2 * (s3 * y * z);
    yv[7]  = f2 * (0.5f * s3) * (z2 - x2);
    yv[8]  = f3 * (c3 * x * (3.0f * z2 - x2));
    yv[9]  = f3 * (s15 * x * y * z);
    yv[10] = f3 * (c1 * x * (4.0f * y2 - x2 - z2));
    yv[11] = f3 * (0.5f * y * (2.0f * y2 - 3.0f * x2 - 3.0f * z2));
    yv[12] = f3 * (c1 * z * (4.0f * y2 - x2 - z2));
    yv[13] = f3 * (0.5f * s15) * (y * (z2 - x2));
    yv[14] = f3 * (c3 * z * (z2 - 3.0f * x2));

    // hi/lo bf16 split
    unsigned short hb[15], lb[15];
    #pragma unroll
    for (int j = 0; j < 15; j++) {
        __nv_bfloat16 h = __float2bfloat16(yv[j]);
        float hf = __bfloat162float(h);
        __nv_bfloat16 l = __float2bfloat16(yv[j] - hf);
        hb[j] = __bfloat16_as_ushort(h);
        lb[j] = __bfloat16_as_ushort(l);
    }

    // assemble 48 cols: q -> [h|h|l], k -> [h|l|h]; cols 45..63 zero-padded
    unsigned short cols[48];
    #pragma unroll
    for (int j = 0; j < 15; j++) {
        cols[j]      = hb[j];
        cols[15 + j] = which ? lb[j] : hb[j];
        cols[30 + j] = which ? hb[j] : lb[j];
    }
    cols[45] = 0; cols[46] = 0; cols[47] = 0;

    uint32_t u[32];
    #pragma unroll
    for (int i = 0; i < 24; i++)
        u[i] = (uint32_t)cols[2 * i] | ((uint32_t)cols[2 * i + 1] << 16);
    #pragma unroll
    for (int i = 24; i < 32; i++) u[i] = 0;

    __nv_bfloat16* dst = which ? g_Bbf : g_Abf;
    size_t obase = (((size_t)b * HG + hg) * NN + n) * KPAD;
    uint4* o = (uint4*)(dst + obase);
    #pragma unroll
    for (int i = 0; i < 8; i++)
        o[i] = make_uint4(u[4*i], u[4*i+1], u[4*i+2], u[4*i+3]);
}

// ---------------------------------------------------------------------------
// mma.sync bf16 wrapper (m16n8k16, fp32 accum) — portable PTX (compute_103 ok)
// ---------------------------------------------------------------------------
__device__ __forceinline__ void mma_bf16(float* d,
                                         uint32_t a0, uint32_t a1,
                                         uint32_t a2, uint32_t a3,
                                         uint32_t b0, uint32_t b1)
{
    asm volatile(
        "mma.sync.aligned.m16n8k16.row.col.f32.bf16.bf16.f32 "
        "{%0,%1,%2,%3}, {%4,%5,%6,%7}, {%8,%9}, {%0,%1,%2,%3};"
        : "+f"(d[0]), "+f"(d[1]), "+f"(d[2]), "+f"(d[3])
        : "r"(a0), "r"(a1), "r"(a2), "r"(a3), "r"(b0), "r"(b1));
}

// ---------------------------------------------------------------------------
// Kernel 2: strip-persistent batched GEMM on HMMA.
// scores[batch, n, m] = sum_{d<48} A[n,d] * B[m,d]   (both bf16, fp32 accum)
// Block = 128(n) x 512(m) strip, 256 threads (8 warps).
//   A tile (128x48) staged once; B tiles (128x48) double-buffered with
//   register prefetch. smem rows pitch 56 bf16 (112B) -> conflict-free
//   b32 fragment loads ((28g+c) mod 32 is a lane permutation).
// Warp (wid): rows (wid&3)*32 (2 m16 frags), cols (wid>>2)*64 (8 n8 frags).
// D fragments stored directly: STG.64 covers 8 full 32B sectors.
// ---------------------------------------------------------------------------
#define PITCHB 112    // smem row pitch in bytes (56 bf16)

__global__ void __launch_bounds__(256, 2) score_mma_kernel(float* __restrict__ out)
{
    __shared__ __align__(16) char smA[128 * PITCHB];
    __shared__ __align__(16) char smB[2][128 * PITCHB];

    int batch = blockIdx.z;
    int n0 = blockIdx.y * 128;
    int ms = blockIdx.x * 512;
    int tid = threadIdx.x;

    const uint4* Ag = (const uint4*)(g_Abf + (size_t)batch * NN * KPAD);
    const uint4* Bg = (const uint4*)(g_Bbf + (size_t)batch * NN * KPAD);

    // staging map: 128 rows x 6 chunks(16B) = 768 items, 3 per thread
    int srow[3], sch[3];
    #pragma unroll
    for (int i = 0; i < 3; i++) {
        int idx = tid + i * 256;
        srow[i] = idx / 6;
        sch[i]  = idx % 6;
    }

    // ---- prologue: stage A and B tile 0 ----
    #pragma unroll
    for (int i = 0; i < 3; i++) {
        uint4 va = Ag[(size_t)(n0 + srow[i]) * 8 + sch[i]];
        uint4 vb = Bg[(size_t)(ms + srow[i]) * 8 + sch[i]];
        *(uint4*)(smA    + srow[i] * PITCHB + sch[i] * 16) = va;
        *(uint4*)(smB[0] + srow[i] * PITCHB + sch[i] * 16) = vb;
    }
    __syncthreads();

    int lane = tid & 31;
    int wid  = tid >> 5;
    int g = lane >> 2;            // 0..7
    int c = lane & 3;             // 0..3
    int wrow = (wid & 3) * 32;    // warp row base
    int wcol = (wid >> 2) * 64;   // warp col base within 128-col tile

    float* obase = out + (size_t)batch * NN * NN;

    #pragma unroll 1
    for (int j = 0; j < 4; j++) {
        const char* sB = smB[j & 1];

        // prefetch next B tile into registers (hidden by MMA below)
        uint4 p[3];
        if (j < 3) {
            #pragma unroll
            for (int i = 0; i < 3; i++)
                p[i] = Bg[(size_t)(ms + (j + 1) * 128 + srow[i]) * 8 + sch[i]];
        }

        // ---- compute 128x128 tile: acc[mf][nf][4] ----
        float acc[2][8][4];
        #pragma unroll
        for (int mf = 0; mf < 2; mf++)
            #pragma unroll
            for (int nf = 0; nf < 8; nf++)
                #pragma unroll
                for (int e = 0; e < 4; e++) acc[mf][nf][e] = 0.0f;

        #pragma unroll
        for (int s = 0; s < 3; s++) {
            int k0 = s * 16;
            int koff = (k0 + 2 * c) * 2;      // byte offset of k pair

            uint32_t a[2][4];
            #pragma unroll
            for (int mf = 0; mf < 2; mf++) {
                const char* base0 = smA + (wrow + mf * 16 + g) * PITCHB + koff;
                const char* base1 = base0 + 8 * PITCHB;
                a[mf][0] = *(const uint32_t*)(base0);        // row g,   k
                a[mf][1] = *(const uint32_t*)(base1);        // row g+8, k
                a[mf][2] = *(const uint32_t*)(base0 + 16);   // row g,   k+8
                a[mf][3] = *(const uint32_t*)(base1 + 16);   // row g+8, k+8
            }

            #pragma unroll
            for (int nf = 0; nf < 8; nf++) {
                const char* bb = sB + (wcol + nf * 8 + g) * PITCHB + koff;
                uint32_t b0 = *(const uint32_t*)(bb);        // col g, k
                uint32_t b1 = *(const uint32_t*)(bb + 16);   // col g, k+8
                mma_bf16(acc[0][nf], a[0][0], a[0][1], a[0][2], a[0][3], b0, b1);
                mma_bf16(acc[1][nf], a[1][0], a[1][1], a[1][2], a[1][3], b0, b1);
            }
        }

        // ---- store tile j: per frag two STG.64 (full 32B sectors) ----
        int mcol = ms + j * 128;
        #pragma unroll
        for (int mf = 0; mf < 2; mf++) {
            int row0 = n0 + wrow + mf * 16 + g;
            float* r0 = obase + (size_t)row0 * NN;
            float* r1 = r0 + 8 * NN;
            #pragma unroll
            for (int nf = 0; nf < 8; nf++) {
                int col = mcol + wcol + nf * 8 + 2 * c;
                __stcs((float2*)(r0 + col),
                       make_float2(acc[mf][nf][0], acc[mf][nf][1]));
                __stcs((float2*)(r1 + col),
                       make_float2(acc[mf][nf][2], acc[mf][nf][3]));
            }
        }

        // ---- publish prefetched tile into the other buffer ----
        if (j < 3) {
            char* nB = smB[(j + 1) & 1];
            #pragma unroll
            for (int i = 0; i < 3; i++)
                *(uint4*)(nB + srow[i] * PITCHB + sch[i] * 16) = p[i];
            __syncthreads();
        }
    }
}

// ---------------------------------------------------------------------------
extern "C" void kernel_launch(void* const* d_in, const int* in_sizes, int n_in,
                              void* d_out, int out_size)
{
    const float* q  = (const float*)d_in[0];
    const float* k  = (const float*)d_in[1];
    const float* rq = (const float*)d_in[2];
    const float* rk = (const float*)d_in[3];
    float* out = (float*)d_out;

    int blocks = (2 * NROWS + 255) / 256;
    sh_expand_kernel<<<blocks, 256>>>(q, k, rq, rk);

    dim3 grid(NN / 512, NN / 128, NBATCH);  // 2 x 8 x 128 = 2048 blocks
    score_mma_kernel<<<grid, 256>>>(out);
}

// round 9
// speedup vs baseline: 1.1156x; 1.1156x over previous
#include <cuda_runtime.h>
#include <cuda_bf16.h>
#include <math.h>
#include <cstdint>

// Problem dims (fixed by the reference setup_inputs)
#define BB   2
#define NN   1024
#define HG   64            // H*G
#define NBATCH (BB*HG)     // 128 independent GEMM batches
#define NROWS  (BB*NN*HG)  // 131072 SH rows per side
#define KPAD 64            // 48 used (h|h|l or h|l|h), padded to 64 bf16 rows
#define KTOT 48            // active K (3 x 16)

// bf16 hi/lo operand arrays, [batch][n][KPAD], K-contiguous rows
__device__ __nv_bfloat16 g_Abf[(size_t)NBATCH * NN * KPAD];  // q side (scaled)
__device__ __nv_bfloat16 g_Bbf[(size_t)NBATCH * NN * KPAD];  // k side

// ---------------------------------------------------------------------------
// Kernel 1: rotate -> normalize -> SH -> bf16 hi/lo split -> K-padded rows.
//   q side (which=0): cols [h,h,l] of Y/sqrt(15)  -> g_Abf
//   k side (which=1): cols [h,l,h] of Y           -> g_Bbf
// Dot over 48 cols then gives h.h + h.l + l.h  (compensated bf16 product).
// ---------------------------------------------------------------------------
__global__ void sh_expand_kernel(const float* __restrict__ q_in,
                                 const float* __restrict__ k_in,
                                 const float* __restrict__ rq_in,
                                 const float* __restrict__ rk_in)
{
    int gt = blockIdx.x * blockDim.x + threadIdx.x;
    if (gt >= 2 * NROWS) return;
    int which = gt >= NROWS;          // 0 -> q, 1 -> k
    int t = gt - which * NROWS;

    const float* v_in = which ? k_in : q_in;
    const float* r_in = which ? rk_in : rq_in;
    float scale = which ? 1.0f : 0.2581988897471611f;  // 1/sqrt(15)

    int hg = t & (HG - 1);       // h*G + g
    int bn = t >> 6;             // b*N + n
    int b  = bn >> 10;           // /N
    int n  = bn & (NN - 1);

    const float* q = v_in + (size_t)t * 3;
    const float* r = r_in + (size_t)bn * 9;
    float q0 = q[0], q1 = q[1], q2 = q[2];

    float vx = r[0]*q0 + r[1]*q1 + r[2]*q2;
    float vy = r[3]*q0 + r[4]*q1 + r[5]*q2;
    float vz = r[6]*q0 + r[7]*q1 + r[8]*q2;

    float nrm = sqrtf(vx*vx + vy*vy + vz*vz);
    float inv = 1.0f / fmaxf(nrm, 1e-12f);
    float x = vx*inv, y = vy*inv, z = vz*inv;
    float x2 = x*x, y2 = y*y, z2 = z*z;

    const float f1 = 0.4886025119029199f * scale;  // sqrt(3/(4pi))
    const float f2 = 0.6307831305050401f * scale;  // sqrt(5/(4pi))
    const float f3 = 0.7463526651802308f * scale;  // sqrt(7/(4pi))
    const float s3  = 1.7320508075688772f;
    const float s15 = 3.8729833462074170f;
    const float c1  = 0.6123724356957945f;         // sqrt(3/8)
    const float c3  = 0.7905694150420949f;         // sqrt(5/8)

    float yv[15];
    yv[0]  = f1 * x;
    yv[1]  = f1 * y;
    yv[2]  = f1 * z;
    yv[3]  = f2 * (s3 * x * z);
    yv[4]  = f2 * (s3 * x * y);
    yv[5]  = f2 * (y2 - 0.5f * (x2 + z2));
    yv[6]  = f2 * (s3 * y * z);
    yv[7]  = f2 * (0.5f * s3) * (z2 - x2);
    yv[8]  = f3 * (c3 * x * (3.0f * z2 - x2));
    yv[9]  = f3 * (s15 * x * y * z);
    yv[10] = f3 * (c1 * x * (4.0f * y2 - x2 - z2));
    yv[11] = f3 * (0.5f * y * (2.0f * y2 - 3.0f * x2 - 3.0f * z2));
    yv[12] = f3 * (c1 * z * (4.0f * y2 - x2 - z2));
    yv[13] = f3 * (0.5f * s15) * (y * (z2 - x2));
    yv[14] = f3 * (c3 * z * (z2 - 3.0f * x2));

    // hi/lo bf16 split
    unsigned short hb[15], lb[15];
    #pragma unroll
    for (int j = 0; j < 15; j++) {
        __nv_bfloat16 h = __float2bfloat16(yv[j]);
        float hf = __bfloat162float(h);
        __nv_bfloat16 l = __float2bfloat16(yv[j] - hf);
        hb[j] = __bfloat16_as_ushort(h);
        lb[j] = __bfloat16_as_ushort(l);
    }

    // assemble 48 cols: q -> [h|h|l], k -> [h|l|h]; cols 45..63 zero-padded
    unsigned short cols[48];
    #pragma unroll
    for (int j = 0; j < 15; j++) {
        cols[j]      = hb[j];
        cols[15 + j] = which ? lb[j] : hb[j];
        cols[30 + j] = which ? hb[j] : lb[j];
    }
    cols[45] = 0; cols[46] = 0; cols[47] = 0;

    uint32_t u[32];
    #pragma unroll
    for (int i = 0; i < 24; i++)
        u[i] = (uint32_t)cols[2 * i] | ((uint32_t)cols[2 * i + 1] << 16);
    #pragma unroll
    for (int i = 24; i < 32; i++) u[i] = 0;

    __nv_bfloat16* dst = which ? g_Bbf : g_Abf;
    size_t obase = (((size_t)b * HG + hg) * NN + n) * KPAD;
    uint4* o = (uint4*)(dst + obase);
    #pragma unroll
    for (int i = 0; i < 8; i++)
        o[i] = make_uint4(u[4*i], u[4*i+1], u[4*i+2], u[4*i+3]);
}

// ---------------------------------------------------------------------------
// mma.sync bf16 wrapper (m16n8k16, fp32 accum) — portable PTX (compute_103 ok)
// ---------------------------------------------------------------------------
__device__ __forceinline__ void mma_bf16(float* d,
                                         uint32_t a0, uint32_t a1,
                                         uint32_t a2, uint32_t a3,
                                         uint32_t b0, uint32_t b1)
{
    asm volatile(
        "mma.sync.aligned.m16n8k16.row.col.f32.bf16.bf16.f32 "
        "{%0,%1,%2,%3}, {%4,%5,%6,%7}, {%8,%9}, {%0,%1,%2,%3};"
        : "+f"(d[0]), "+f"(d[1]), "+f"(d[2]), "+f"(d[3])
        : "r"(a0), "r"(a1), "r"(a2), "r"(a3), "r"(b0), "r"(b1));
}

// B column permutation: actual tile-local col w = {g6}{h:2}{c:2}{d:2}
// -> smem row f = {g6}{h:2}{d1}{c:2}{d0}.  MMA D fragment col f then holds the
// score for actual col w, and thread c = lane&3 ends up owning the contiguous
// 16-float span cols 16h+4c+d per (h), enabling STG.128 output stores.
__device__ __forceinline__ int bperm(int w)
{
    return (w & 0x70) | ((w & 2) << 2) | ((w & 0xC) >> 1) | (w & 1);
}

// ---------------------------------------------------------------------------
// Kernel 2: strip-persistent batched GEMM on HMMA.
// scores[batch, n, m] = sum_{d<48} A[n,d] * B[m,d]   (both bf16, fp32 accum)
// Block = 128(n) x 512(m) strip, 256 threads (8 warps).
//   A tile (128x48) staged once; B tiles (128x48) double-buffered with
//   register prefetch, B columns permuted per bperm(). smem row pitch 56 bf16
//   (112B) -> conflict-free b32 fragment loads.
// Warp (wid): rows (wid&3)*32 (2 m16 frags), cols (wid>>2)*64 (8 n8 frags).
// D stored as 16 STG.128 per thread per tile (full 64B row segments).
// ---------------------------------------------------------------------------
#define PITCHB 112    // smem row pitch in bytes (56 bf16)

__global__ void __launch_bounds__(256, 2) score_mma_kernel(float* __restrict__ out)
{
    __shared__ __align__(16) char smA[128 * PITCHB];
    __shared__ __align__(16) char smB[2][128 * PITCHB];

    int batch = blockIdx.z;
    int n0 = blockIdx.y * 128;
    int ms = blockIdx.x * 512;
    int tid = threadIdx.x;

    const uint4* Ag = (const uint4*)(g_Abf + (size_t)batch * NN * KPAD);
    const uint4* Bg = (const uint4*)(g_Bbf + (size_t)batch * NN * KPAD);

    // staging map: 128 rows x 6 chunks(16B) = 768 items, 3 per thread
    int srow[3], sch[3], sdst[3];
    #pragma unroll
    for (int i = 0; i < 3; i++) {
        int idx = tid + i * 256;
        srow[i] = idx / 6;
        sch[i]  = idx % 6;
        sdst[i] = bperm(srow[i]);       // permuted smem row for B
    }

    // ---- prologue: stage A and B tile 0 ----
    #pragma unroll
    for (int i = 0; i < 3; i++) {
        uint4 va = Ag[(size_t)(n0 + srow[i]) * 8 + sch[i]];
        uint4 vb = Bg[(size_t)(ms + srow[i]) * 8 + sch[i]];
        *(uint4*)(smA    + srow[i] * PITCHB + sch[i] * 16) = va;
        *(uint4*)(smB[0] + sdst[i] * PITCHB + sch[i] * 16) = vb;
    }
    __syncthreads();

    int lane = tid & 31;
    int wid  = tid >> 5;
    int g = lane >> 2;            // 0..7
    int c = lane & 3;             // 0..3
    int wrow = (wid & 3) * 32;    // warp row base
    int wcol = (wid >> 2) * 64;   // warp col base within 128-col tile

    float* obase = out + (size_t)batch * NN * NN;

    #pragma unroll 1
    for (int j = 0; j < 4; j++) {
        const char* sB = smB[j & 1];

        // prefetch next B tile into registers (hidden by MMA below)
        uint4 p[3];
        if (j < 3) {
            #pragma unroll
            for (int i = 0; i < 3; i++)
                p[i] = Bg[(size_t)(ms + (j + 1) * 128 + srow[i]) * 8 + sch[i]];
        }

        // ---- compute 128x128 tile: acc[mf][nf][4] ----
        float acc[2][8][4];
        #pragma unroll
        for (int mf = 0; mf < 2; mf++)
            #pragma unroll
            for (int nf = 0; nf < 8; nf++)
                #pragma unroll
                for (int e = 0; e < 4; e++) acc[mf][nf][e] = 0.0f;

        #pragma unroll
        for (int s = 0; s < 3; s++) {
            int k0 = s * 16;
            int koff = (k0 + 2 * c) * 2;      // byte offset of k pair

            uint32_t a[2][4];
            #pragma unroll
            for (int mf = 0; mf < 2; mf++) {
                const char* base0 = smA + (wrow + mf * 16 + g) * PITCHB + koff;
                const char* base1 = base0 + 8 * PITCHB;
                a[mf][0] = *(const uint32_t*)(base0);        // row g,   k
                a[mf][1] = *(const uint32_t*)(base1);        // row g+8, k
                a[mf][2] = *(const uint32_t*)(base0 + 16);   // row g,   k+8
                a[mf][3] = *(const uint32_t*)(base1 + 16);   // row g+8, k+8
            }

            #pragma unroll
            for (int nf = 0; nf < 8; nf++) {
                const char* bb = sB + (wcol + nf * 8 + g) * PITCHB + koff;
                uint32_t b0 = *(const uint32_t*)(bb);        // col g, k
                uint32_t b1 = *(const uint32_t*)(bb + 16);   // col g, k+8
                mma_bf16(acc[0][nf], a[0][0], a[0][1], a[0][2], a[0][3], b0, b1);
                mma_bf16(acc[1][nf], a[1][0], a[1][1], a[1][2], a[1][3], b0, b1);
            }
        }

        // ---- store tile j: permuted layout -> 16 STG.128 per thread ----
        // thread owns cols mcol + wcol + 16h + 4c + {0..3}, h = 0..3,
        // value for (h, d): nf = 2h + (d>>1), e = d&1.
        int mcol = ms + j * 128;
        #pragma unroll
        for (int mf = 0; mf < 2; mf++) {
            #pragma unroll
            for (int r2 = 0; r2 < 2; r2++) {
                float* rp = obase
                          + (size_t)(n0 + wrow + mf * 16 + g + 8 * r2) * NN
                          + mcol + wcol + 4 * c;
                #pragma unroll
                for (int h = 0; h < 4; h++) {
                    float4 v = make_float4(acc[mf][2*h    ][2*r2    ],
                                           acc[mf][2*h    ][2*r2 + 1],
                                           acc[mf][2*h + 1][2*r2    ],
                                           acc[mf][2*h + 1][2*r2 + 1]);
                    __stcs((float4*)(rp + 16 * h), v);
                }
            }
        }

        // ---- publish prefetched tile into the other buffer (permuted) ----
        if (j < 3) {
            char* nB = smB[(j + 1) & 1];
            #pragma unroll
            for (int i = 0; i < 3; i++)
                *(uint4*)(nB + sdst[i] * PITCHB + sch[i] * 16) = p[i];
            __syncthreads();
        }
    }
}

// ---------------------------------------------------------------------------
extern "C" void kernel_launch(void* const* d_in, const int* in_sizes, int n_in,
                              void* d_out, int out_size)
{
    const float* q  = (const float*)d_in[0];
    const float* k  = (const float*)d_in[1];
    const float* rq = (const float*)d_in[2];
    const float* rk = (const float*)d_in[3];
    float* out = (float*)d_out;

    int blocks = (2 * NROWS + 255) / 256;
    sh_expand_kernel<<<blocks, 256>>>(q, k, rq, rk);

    dim3 grid(NN / 512, NN / 128, NBATCH);  // 2 x 8 x 128 = 2048 blocks
    score_mma_kernel<<<grid, 256>>>(out);
}